// round 1
// baseline (speedup 1.0000x reference)
#include <cuda_runtime.h>
#include <math.h>
#include <stdint.h>

#define NN 50000
#define EE 800000
#define INF_F 128
#define OUTF 64
#define HH 4
#define DD 16

// ---------------- device scratch (no allocations allowed) ----------------
__device__ float g_q[NN * OUTF];
__device__ float g_k[NN * OUTF];
__device__ float g_v[NN * OUTF];
__device__ float g_att[NN * OUTF];
__device__ float g_qq[NN * HH];
__device__ float g_kk[NN * HH];
__device__ int   g_cnt[NN];
__device__ int   g_rs[NN + 1];
__device__ int   g_cur[NN];
__device__ int   g_csr[EE];
__device__ int   g_is64;

// ---------------- edge_index dtype detection (int64 vs int32) ----------------
// If the buffer is really int32, reading it as int64 packs two indices into one
// word -> value >= 2^32 with overwhelming probability over 1024 words.
__global__ void detect_kernel(const void* ei) {
    int lane = threadIdx.x;
    const long long* e64 = (const long long*)ei;
    int ok = 1;
    for (int t = lane; t < 1024; t += 32) {
        long long v = e64[t];
        if (v < 0 || v >= NN) ok = 0;
    }
    unsigned b = __ballot_sync(0xffffffffu, ok);
    if (lane == 0) g_is64 = (b == 0xffffffffu) ? 1 : 0;
}

__device__ __forceinline__ int load_idx(const void* ei, int is64, long long pos) {
    return is64 ? (int)((const long long*)ei)[pos] : ((const int*)ei)[pos];
}

// ---------------- fused QKV projection ----------------
// block = 192 threads (thread = one output column among q|k|v), tile = 8 rows.
// W rows read via float4 (L1-resident, 96KB total), x tile in smem (broadcast LDS).
__global__ __launch_bounds__(192) void qkv_kernel(
    const float* __restrict__ x,
    const float* __restrict__ Wq, const float* __restrict__ bq,
    const float* __restrict__ Wk, const float* __restrict__ bk,
    const float* __restrict__ Wv, const float* __restrict__ bv)
{
    __shared__ float xs[8 * 128];
    int tid = threadIdx.x;
    int sel = tid >> 6;   // 0 -> q, 1 -> k, 2 -> v
    int cc  = tid & 63;

    const float* W;
    const float* bias;
    float* out;
    if (sel == 0)      { W = Wq; bias = bq; out = g_q; }
    else if (sel == 1) { W = Wk; bias = bk; out = g_k; }
    else               { W = Wv; bias = bv; out = g_v; }

    int tile = blockIdx.x;                  // 6250 tiles, 8 rows each = 50000 exactly
    const float4* xg4 = (const float4*)(x + (size_t)tile * 8 * 128);
    float4* xs4 = (float4*)xs;
    for (int i = tid; i < 256; i += 192) xs4[i] = xg4[i];
    __syncthreads();

    float b = bias[cc];
    float acc[8];
#pragma unroll
    for (int r = 0; r < 8; r++) acc[r] = b;

    const float4* Wr = (const float4*)(W + cc * 128);
#pragma unroll 4
    for (int k4 = 0; k4 < 32; k4++) {
        float4 w = Wr[k4];
#pragma unroll
        for (int r = 0; r < 8; r++) {
            float4 xv = *(const float4*)(xs + r * 128 + k4 * 4);
            acc[r] = fmaf(w.x, xv.x, fmaf(w.y, xv.y, fmaf(w.z, xv.z, fmaf(w.w, xv.w, acc[r]))));
        }
    }

    int row0 = tile * 8;
#pragma unroll
    for (int r = 0; r < 8; r++) out[(row0 + r) * 64 + cc] = acc[r];
}

// ---------------- per-(node,head) Minkowski self-products ----------------
__global__ void selfprod_kernel() {
    int idx = blockIdx.x * blockDim.x + threadIdx.x;
    if (idx >= NN * HH) return;
    int n = idx >> 2, h = idx & 3;
    const float* qp = g_q + n * 64 + h * 16;
    const float* kp = g_k + n * 64 + h * 16;
    float sq = 0.f, sk = 0.f;
#pragma unroll
    for (int d = 0; d < 15; d++) { sq = fmaf(qp[d], qp[d], sq); sk = fmaf(kp[d], kp[d], sk); }
    sq = fmaf(-qp[15], qp[15], sq);
    sk = fmaf(-kp[15], kp[15], sk);
    g_qq[idx] = sq;
    g_kk[idx] = sk;
}

// ---------------- CSR build ----------------
__global__ void zero_cnt_kernel() {
    int i = blockIdx.x * blockDim.x + threadIdx.x;
    if (i < NN) g_cnt[i] = 0;
}

__global__ void hist_kernel(const void* ei) {
    int is64 = g_is64;
    int e = blockIdx.x * blockDim.x + threadIdx.x;
    if (e >= EE) return;
    int dst = load_idx(ei, is64, (long long)EE + e);
    atomicAdd(&g_cnt[dst], 1);
}

// single-block exclusive scan over 50000 counters (writes row_start + cursor)
__global__ __launch_bounds__(1024) void scan_kernel() {
    __shared__ int warp_sums[32];
    __shared__ int carry_s;
    int tid = threadIdx.x;
    if (tid == 0) carry_s = 0;
    __syncthreads();
    int lane = tid & 31, w = tid >> 5;
    for (int base = 0; base < NN; base += 1024) {
        int i = base + tid;
        int v = (i < NN) ? g_cnt[i] : 0;
        int xsc = v;
#pragma unroll
        for (int o = 1; o < 32; o <<= 1) {
            int t = __shfl_up_sync(0xffffffffu, xsc, o);
            if (lane >= o) xsc += t;
        }
        if (lane == 31) warp_sums[w] = xsc;
        __syncthreads();
        if (w == 0) {
            int y = warp_sums[lane];
#pragma unroll
            for (int o = 1; o < 32; o <<= 1) {
                int t = __shfl_up_sync(0xffffffffu, y, o);
                if (lane >= o) y += t;
            }
            warp_sums[lane] = y;
        }
        __syncthreads();
        int incl = xsc + (w > 0 ? warp_sums[w - 1] : 0);
        int excl = incl - v + carry_s;
        if (i < NN) { g_rs[i] = excl; g_cur[i] = excl; }
        __syncthreads();
        if (tid == 1023) carry_s += incl;
        __syncthreads();
    }
    if (tid == 0) g_rs[NN] = carry_s;
}

__global__ void scatter_kernel(const void* ei) {
    int is64 = g_is64;
    int e = blockIdx.x * blockDim.x + threadIdx.x;
    if (e >= EE) return;
    int src = load_idx(ei, is64, e);
    int dst = load_idx(ei, is64, (long long)EE + e);
    int pos = atomicAdd(&g_cur[dst], 1);
    g_csr[pos] = src;
}

// ---------------- gather attention: one warp per dst node, online softmax ----
// lane l owns flat features {2l, 2l+1}; head h = l/8; 8-lane groups reduce dots.
// Softmax denom cancels exactly into the L2 norm: att = S / (||S|| + EPS*s).
__global__ __launch_bounds__(256) void attn_kernel() {
    int gtid = blockIdx.x * blockDim.x + threadIdx.x;
    int i = gtid >> 5;
    if (i >= NN) return;
    int lane = threadIdx.x & 31;
    int h  = lane >> 3;
    int dp = lane & 7;

    float2 kv = *(const float2*)(g_k + i * 64 + 2 * lane);
    float sign = (dp == 7) ? -1.f : 1.f;   // d = 2*dp+1 == 15 -> Minkowski minus
    float kkv = g_kk[i * 4 + h];

    int js = g_rs[i], je = g_rs[i + 1];

    float m = -INFINITY;
    float s = 0.f, a0 = 0.f, a1 = 0.f;

    for (int j = js; j < je; j++) {
        int src = g_csr[j];
        float2 qv = *(const float2*)(g_q + src * 64 + 2 * lane);
        float part = fmaf(qv.x, kv.x, sign * qv.y * kv.y);
        part += __shfl_xor_sync(0xffffffffu, part, 1);
        part += __shfl_xor_sync(0xffffffffu, part, 2);
        part += __shfl_xor_sync(0xffffffffu, part, 4);
        // part == Minkowski <q_src, k_i> for head h (same in all 8 lanes of group)
        float qqv = g_qq[src * 4 + h];
        float den = qqv * kkv;
        float ratio = (part * part) / fmaxf(fabsf(den), 1e-9f);
        float arg = fmaxf(sqrtf(ratio + 1e-9f), 1.0f + 1e-6f);
        float score = -__logf(arg + sqrtf(fmaf(arg, arg, -1.0f)));  // -acosh(arg)

        float mn = fmaxf(m, score);
        float c = __expf(m - mn);        // exp(-inf)=0 handles first edge
        float p = __expf(score - mn);
        float2 vv = *(const float2*)(g_v + src * 64 + 2 * lane);
        s  = fmaf(s, c, p);
        a0 = fmaf(a0, c, p * vv.x);
        a1 = fmaf(a1, c, p * vv.y);
        m = mn;
    }

    float nsq = fmaf(a0, a0, a1 * a1);
    nsq += __shfl_xor_sync(0xffffffffu, nsq, 1);
    nsq += __shfl_xor_sync(0xffffffffu, nsq, 2);
    nsq += __shfl_xor_sync(0xffffffffu, nsq, 4);
    float norm = sqrtf(nsq);
    // agg = S/s, attended = agg/(||agg||+EPS) = S/(||S|| + EPS*s); 0 if no mass
    float scale = (norm > 0.f) ? 1.f / (norm + 1e-9f * s) : 0.f;
    float2 o;
    o.x = a0 * scale;
    o.y = a1 * scale;
    *(float2*)(g_att + i * 64 + 2 * lane) = o;
}

// ---------------- output projection: [N,64] x [64,64]^T + bias ----------------
__global__ __launch_bounds__(64) void out_kernel(
    const float* __restrict__ Wo, const float* __restrict__ bo,
    float* __restrict__ out)
{
    __shared__ float as[16 * 64];
    int tid = threadIdx.x;          // column
    int tile = blockIdx.x;          // 3125 tiles * 16 rows = 50000 exactly
    const float4* ag = (const float4*)(g_att + (size_t)tile * 16 * 64);
    float4* as4 = (float4*)as;
    for (int i = tid; i < 256; i += 64) as4[i] = ag[i];
    __syncthreads();

    float b = bo[tid];
    float acc[16];
#pragma unroll
    for (int r = 0; r < 16; r++) acc[r] = b;

    const float4* Wr = (const float4*)(Wo + tid * 64);
#pragma unroll 4
    for (int k4 = 0; k4 < 16; k4++) {
        float4 w = Wr[k4];
#pragma unroll
        for (int r = 0; r < 16; r++) {
            float4 a = *(const float4*)(as + r * 64 + k4 * 4);
            acc[r] = fmaf(w.x, a.x, fmaf(w.y, a.y, fmaf(w.z, a.z, fmaf(w.w, a.w, acc[r]))));
        }
    }

    int row0 = tile * 16;
#pragma unroll
    for (int r = 0; r < 16; r++) out[(row0 + r) * 64 + tid] = acc[r];
}

// ---------------- launch ----------------
extern "C" void kernel_launch(void* const* d_in, const int* in_sizes, int n_in,
                              void* d_out, int out_size) {
    const float* x  = (const float*)d_in[0];
    const void*  ei = d_in[1];
    const float* Wq = (const float*)d_in[2];
    const float* bq = (const float*)d_in[3];
    const float* Wk = (const float*)d_in[4];
    const float* bk = (const float*)d_in[5];
    const float* Wv = (const float*)d_in[6];
    const float* bv = (const float*)d_in[7];
    const float* Wo = (const float*)d_in[8];
    const float* bo = (const float*)d_in[9];
    float* out = (float*)d_out;

    detect_kernel<<<1, 32>>>(ei);
    qkv_kernel<<<NN / 8, 192>>>(x, Wq, bq, Wk, bk, Wv, bv);
    selfprod_kernel<<<(NN * HH + 255) / 256, 256>>>();
    zero_cnt_kernel<<<(NN + 255) / 256, 256>>>();
    hist_kernel<<<(EE + 255) / 256, 256>>>(ei);
    scan_kernel<<<1, 1024>>>();
    scatter_kernel<<<(EE + 255) / 256, 256>>>(ei);
    attn_kernel<<<(NN * 32) / 256, 256>>>();
    out_kernel<<<NN / 16, 64>>>(Wo, bo, out);
}

// round 2
// speedup vs baseline: 1.0825x; 1.0825x over previous
#include <cuda_runtime.h>
#include <math.h>
#include <stdint.h>

#define NN 50000
#define EE 800000
#define INF_F 128
#define OUTF 64
#define HH 4
#define DD 16

// ---------------- device scratch (no allocations allowed) ----------------
__device__ float g_q[NN * OUTF];
__device__ float g_k[NN * OUTF];
__device__ float g_v[NN * OUTF];
__device__ float g_att[NN * OUTF];
__device__ float g_qq[NN * HH];
__device__ float g_kk[NN * HH];
__device__ int   g_cnt[NN];
__device__ int   g_rs[NN + 1];
__device__ int   g_cur[NN];
__device__ int   g_csr[EE];
__device__ int   g_is64;

// packed f32x2 FMA: d = a*b + c elementwise on packed pairs (Blackwell FFMA2)
__device__ __forceinline__ unsigned long long ffma2(
    unsigned long long a, unsigned long long b, unsigned long long c)
{
    unsigned long long d;
    asm("fma.rn.f32x2 %0, %1, %2, %3;" : "=l"(d) : "l"(a), "l"(b), "l"(c));
    return d;
}

__device__ __forceinline__ float unpack_sum(unsigned long long a) {
    float lo = __uint_as_float((unsigned)(a & 0xffffffffu));
    float hi = __uint_as_float((unsigned)(a >> 32));
    return lo + hi;
}

__device__ __forceinline__ int load_idx(const void* ei, int is64, long long pos) {
    return is64 ? (int)((const long long*)ei)[pos] : ((const int*)ei)[pos];
}

// ---------------- prep: zero histogram + edge dtype detection -------------
// If edge_index is really int32, reading it as int64 packs two indices into one
// word -> out-of-range with overwhelming probability over 1024 words.
__global__ void prep_kernel(const void* ei) {
    int i = blockIdx.x * blockDim.x + threadIdx.x;
    if (i < NN) g_cnt[i] = 0;
    if (blockIdx.x == 0 && threadIdx.x < 32) {
        int lane = threadIdx.x;
        const long long* e64 = (const long long*)ei;
        int ok = 1;
        for (int t = lane; t < 1024; t += 32) {
            long long v = e64[t];
            if (v < 0 || v >= NN) ok = 0;
        }
        unsigned b = __ballot_sync(0xffffffffu, ok);
        if (lane == 0) g_is64 = (b == 0xffffffffu) ? 1 : 0;
    }
}

// ---------------- fused QKV projection + Minkowski self-products ----------
// block = 192 threads (thread = one output column among q|k|v), tile = 8 rows.
// Inner product accumulated as packed f32x2 pairs along K (FFMA2, 2x rate).
__global__ __launch_bounds__(192) void qkv_kernel(
    const float* __restrict__ x,
    const float* __restrict__ Wq, const float* __restrict__ bq,
    const float* __restrict__ Wk, const float* __restrict__ bk,
    const float* __restrict__ Wv, const float* __restrict__ bv)
{
    __shared__ __align__(16) float xs[8 * 128];
    int tid = threadIdx.x;
    int sel = tid >> 6;   // 0 -> q, 1 -> k, 2 -> v
    int cc  = tid & 63;

    const float* W;
    const float* bias;
    float* out;
    if (sel == 0)      { W = Wq; bias = bq; out = g_q; }
    else if (sel == 1) { W = Wk; bias = bk; out = g_k; }
    else               { W = Wv; bias = bv; out = g_v; }

    int tile = blockIdx.x;                  // 6250 tiles * 8 rows = 50000 exactly
    const float4* xg4 = (const float4*)(x + (size_t)tile * 8 * 128);
    float4* xs4 = (float4*)xs;
    for (int i = tid; i < 256; i += 192) xs4[i] = xg4[i];
    __syncthreads();

    unsigned long long acc[8];
#pragma unroll
    for (int r = 0; r < 8; r++) acc[r] = 0ull;

    const ulonglong2* Wr = (const ulonglong2*)(W + cc * 128);
    const ulonglong2* xs2 = (const ulonglong2*)xs;
#pragma unroll 4
    for (int k4 = 0; k4 < 32; k4++) {
        ulonglong2 w = Wr[k4];
#pragma unroll
        for (int r = 0; r < 8; r++) {
            ulonglong2 xv = xs2[r * 32 + k4];
            acc[r] = ffma2(w.x, xv.x, acc[r]);
            acc[r] = ffma2(w.y, xv.y, acc[r]);
        }
    }

    float b = bias[cc];
    float res[8];
#pragma unroll
    for (int r = 0; r < 8; r++) res[r] = unpack_sum(acc[r]) + b;

    int row0 = tile * 8;
#pragma unroll
    for (int r = 0; r < 8; r++) out[(row0 + r) * 64 + cc] = res[r];

    // fused Minkowski self-products for q and k: reduce over the 16 lanes of
    // each head (warp lanes span 32 consecutive cc -> lane group == head chunk)
    if (sel < 2) {
        float sign = ((cc & 15) == 15) ? -1.f : 1.f;
        float* dst = (sel == 0) ? g_qq : g_kk;
        int h = cc >> 4;
#pragma unroll
        for (int r = 0; r < 8; r++) {
            float p = res[r] * res[r] * sign;
            p += __shfl_xor_sync(0xffffffffu, p, 1);
            p += __shfl_xor_sync(0xffffffffu, p, 2);
            p += __shfl_xor_sync(0xffffffffu, p, 4);
            p += __shfl_xor_sync(0xffffffffu, p, 8);
            if ((cc & 15) == 0) dst[(row0 + r) * 4 + h] = p;
        }
    }
}

// ---------------- CSR build ----------------
__global__ void hist_kernel(const void* ei) {
    int is64 = g_is64;
    int e = blockIdx.x * blockDim.x + threadIdx.x;
    if (e >= EE) return;
    int dst = load_idx(ei, is64, (long long)EE + e);
    atomicAdd(&g_cnt[dst], 1);
}

// single-block exclusive scan over 50000 counters (writes row_start + cursor)
__global__ __launch_bounds__(1024) void scan_kernel() {
    __shared__ int warp_sums[32];
    __shared__ int carry_s;
    int tid = threadIdx.x;
    if (tid == 0) carry_s = 0;
    __syncthreads();
    int lane = tid & 31, w = tid >> 5;
    for (int base = 0; base < NN; base += 1024) {
        int i = base + tid;
        int v = (i < NN) ? g_cnt[i] : 0;
        int xsc = v;
#pragma unroll
        for (int o = 1; o < 32; o <<= 1) {
            int t = __shfl_up_sync(0xffffffffu, xsc, o);
            if (lane >= o) xsc += t;
        }
        if (lane == 31) warp_sums[w] = xsc;
        __syncthreads();
        if (w == 0) {
            int y = warp_sums[lane];
#pragma unroll
            for (int o = 1; o < 32; o <<= 1) {
                int t = __shfl_up_sync(0xffffffffu, y, o);
                if (lane >= o) y += t;
            }
            warp_sums[lane] = y;
        }
        __syncthreads();
        int incl = xsc + (w > 0 ? warp_sums[w - 1] : 0);
        int excl = incl - v + carry_s;
        if (i < NN) { g_rs[i] = excl; g_cur[i] = excl; }
        __syncthreads();
        if (tid == 1023) carry_s += incl;
        __syncthreads();
    }
    if (tid == 0) g_rs[NN] = carry_s;
}

__global__ void scatter_kernel(const void* ei) {
    int is64 = g_is64;
    int e = blockIdx.x * blockDim.x + threadIdx.x;
    if (e >= EE) return;
    int src = load_idx(ei, is64, e);
    int dst = load_idx(ei, is64, (long long)EE + e);
    int pos = atomicAdd(&g_cur[dst], 1);
    g_csr[pos] = src;
}

// ---------------- gather attention: one warp per dst node --------------------
// lane l owns flat features {2l, 2l+1}; head h = l/8; 8-lane groups reduce dots.
// exp(-acosh(arg)) == 1/(arg + sqrt(arg^2-1))  -> no MUFU log/exp at all.
// Softmax denom cancels exactly into the L2 norm: att = S / (||S|| + EPS*s),
// and the max-shift cancels too (scale invariance), so no online max needed.
__global__ __launch_bounds__(256) void attn_kernel() {
    int gtid = blockIdx.x * blockDim.x + threadIdx.x;
    int i = gtid >> 5;
    if (i >= NN) return;
    int lane = threadIdx.x & 31;
    int h  = lane >> 3;
    int dp = lane & 7;

    float2 kv = *(const float2*)(g_k + i * 64 + 2 * lane);
    float sign = (dp == 7) ? -1.f : 1.f;   // flat dim 15 carries Minkowski minus
    float kkv = g_kk[i * 4 + h];

    int js = g_rs[i], je = g_rs[i + 1];

    float s = 0.f, a0 = 0.f, a1 = 0.f;

    int j = js;
    for (; j + 1 < je; j += 2) {
        int s0 = g_csr[j];
        int s1 = g_csr[j + 1];
        float2 q0 = *(const float2*)(g_q + s0 * 64 + 2 * lane);
        float2 q1 = *(const float2*)(g_q + s1 * 64 + 2 * lane);
        float d0 = fmaf(q0.x, kv.x, sign * q0.y * kv.y);
        float d1 = fmaf(q1.x, kv.x, sign * q1.y * kv.y);
        d0 += __shfl_xor_sync(0xffffffffu, d0, 1);
        d1 += __shfl_xor_sync(0xffffffffu, d1, 1);
        d0 += __shfl_xor_sync(0xffffffffu, d0, 2);
        d1 += __shfl_xor_sync(0xffffffffu, d1, 2);
        d0 += __shfl_xor_sync(0xffffffffu, d0, 4);
        d1 += __shfl_xor_sync(0xffffffffu, d1, 4);
        float qq0 = g_qq[s0 * 4 + h];
        float qq1 = g_qq[s1 * 4 + h];
        float2 v0 = *(const float2*)(g_v + s0 * 64 + 2 * lane);
        float2 v1 = *(const float2*)(g_v + s1 * 64 + 2 * lane);

        float r0 = __fdividef(d0 * d0, fmaxf(fabsf(qq0 * kkv), 1e-9f));
        float r1 = __fdividef(d1 * d1, fmaxf(fabsf(qq1 * kkv), 1e-9f));
        float arg0 = fmaxf(sqrtf(r0 + 1e-9f), 1.0f + 1e-6f);
        float arg1 = fmaxf(sqrtf(r1 + 1e-9f), 1.0f + 1e-6f);
        float p0 = __frcp_rn(arg0 + sqrtf(fmaf(arg0, arg0, -1.0f)));
        float p1 = __frcp_rn(arg1 + sqrtf(fmaf(arg1, arg1, -1.0f)));

        s += p0 + p1;
        a0 = fmaf(p0, v0.x, fmaf(p1, v1.x, a0));
        a1 = fmaf(p0, v0.y, fmaf(p1, v1.y, a1));
    }
    if (j < je) {
        int s0 = g_csr[j];
        float2 q0 = *(const float2*)(g_q + s0 * 64 + 2 * lane);
        float d0 = fmaf(q0.x, kv.x, sign * q0.y * kv.y);
        d0 += __shfl_xor_sync(0xffffffffu, d0, 1);
        d0 += __shfl_xor_sync(0xffffffffu, d0, 2);
        d0 += __shfl_xor_sync(0xffffffffu, d0, 4);
        float qq0 = g_qq[s0 * 4 + h];
        float2 v0 = *(const float2*)(g_v + s0 * 64 + 2 * lane);
        float r0 = __fdividef(d0 * d0, fmaxf(fabsf(qq0 * kkv), 1e-9f));
        float arg0 = fmaxf(sqrtf(r0 + 1e-9f), 1.0f + 1e-6f);
        float p0 = __frcp_rn(arg0 + sqrtf(fmaf(arg0, arg0, -1.0f)));
        s += p0;
        a0 = fmaf(p0, v0.x, a0);
        a1 = fmaf(p0, v0.y, a1);
    }

    float nsq = fmaf(a0, a0, a1 * a1);
    nsq += __shfl_xor_sync(0xffffffffu, nsq, 1);
    nsq += __shfl_xor_sync(0xffffffffu, nsq, 2);
    nsq += __shfl_xor_sync(0xffffffffu, nsq, 4);
    float norm = sqrtf(nsq);
    // agg = S/s, attended = agg/(||agg||+EPS) = S/(||S|| + EPS*s); 0 if no mass
    float scale = (norm > 0.f) ? __frcp_rn(norm + 1e-9f * s) : 0.f;
    float2 o;
    o.x = a0 * scale;
    o.y = a1 * scale;
    *(float2*)(g_att + i * 64 + 2 * lane) = o;
}

// ---------------- output projection: [N,64] x [64,64]^T + bias --------------
// 256-thread blocks = 4 independent 16-row tiles (64 columns each), FFMA2.
__global__ __launch_bounds__(256) void out_kernel(
    const float* __restrict__ Wo, const float* __restrict__ bo,
    float* __restrict__ out)
{
    __shared__ __align__(16) float as[4][16 * 64];
    int grp = threadIdx.x >> 6;     // tile within block
    int tid = threadIdx.x & 63;     // column
    int tile = blockIdx.x * 4 + grp;
    if (tile >= 3125) return;       // 3125 tiles * 16 rows = 50000

    const float4* ag = (const float4*)(g_att + (size_t)tile * 16 * 64);
    float4* as4 = (float4*)as[grp];
    for (int i = tid; i < 256; i += 64) as4[i] = ag[i];
    __syncwarp();
    // ensure full 64-thread group sees the tile (2 warps per group)
    __syncthreads();

    unsigned long long acc[16];
#pragma unroll
    for (int r = 0; r < 16; r++) acc[r] = 0ull;

    const ulonglong2* Wr = (const ulonglong2*)(Wo + tid * 64);
    const ulonglong2* as2 = (const ulonglong2*)as[grp];
#pragma unroll 4
    for (int k4 = 0; k4 < 16; k4++) {
        ulonglong2 w = Wr[k4];
#pragma unroll
        for (int r = 0; r < 16; r++) {
            ulonglong2 a = as2[r * 16 + k4];
            acc[r] = ffma2(w.x, a.x, acc[r]);
            acc[r] = ffma2(w.y, a.y, acc[r]);
        }
    }

    float b = bo[tid];
    int row0 = tile * 16;
#pragma unroll
    for (int r = 0; r < 16; r++) out[(row0 + r) * 64 + tid] = unpack_sum(acc[r]) + b;
}

// ---------------- launch ----------------
extern "C" void kernel_launch(void* const* d_in, const int* in_sizes, int n_in,
                              void* d_out, int out_size) {
    const float* x  = (const float*)d_in[0];
    const void*  ei = d_in[1];
    const float* Wq = (const float*)d_in[2];
    const float* bq = (const float*)d_in[3];
    const float* Wk = (const float*)d_in[4];
    const float* bk = (const float*)d_in[5];
    const float* Wv = (const float*)d_in[6];
    const float* bv = (const float*)d_in[7];
    const float* Wo = (const float*)d_in[8];
    const float* bo = (const float*)d_in[9];
    float* out = (float*)d_out;

    prep_kernel<<<(NN + 255) / 256, 256>>>(ei);
    qkv_kernel<<<NN / 8, 192>>>(x, Wq, bq, Wk, bk, Wv, bv);
    hist_kernel<<<(EE + 255) / 256, 256>>>(ei);
    scan_kernel<<<1, 1024>>>();
    scatter_kernel<<<(EE + 255) / 256, 256>>>(ei);
    attn_kernel<<<(NN * 32) / 256, 256>>>();
    out_kernel<<<(3125 + 3) / 4, 256>>>(Wo, bo, out);
}

// round 3
// speedup vs baseline: 1.2024x; 1.1107x over previous
#include <cuda_runtime.h>
#include <math.h>
#include <stdint.h>

#define NN 50000
#define EE 800000
#define INF_F 128
#define OUTF 64
#define HH 4
#define DD 16

// ---------------- device scratch (no allocations allowed) ----------------
__device__ float g_q[NN * OUTF];
__device__ float g_k[NN * OUTF];
__device__ float g_v[NN * OUTF];
__device__ float g_att[NN * OUTF];
__device__ float g_qq[NN * HH];
__device__ float g_kk[NN * HH];
__device__ int   g_cnt[NN];
__device__ int   g_rs[NN];
__device__ int   g_cur[NN];
__device__ int   g_csr[EE];
__device__ int   g_is64;
__device__ int   g_total;

// packed f32x2 FMA: d = a*b + c elementwise on packed pairs (Blackwell FFMA2)
__device__ __forceinline__ unsigned long long ffma2(
    unsigned long long a, unsigned long long b, unsigned long long c)
{
    unsigned long long d;
    asm("fma.rn.f32x2 %0, %1, %2, %3;" : "=l"(d) : "l"(a), "l"(b), "l"(c));
    return d;
}

__device__ __forceinline__ float unpack_sum(unsigned long long a) {
    float lo = __uint_as_float((unsigned)(a & 0xffffffffu));
    float hi = __uint_as_float((unsigned)(a >> 32));
    return lo + hi;
}

// ---------------- prep: zero histogram/total + edge dtype detection -------
// If edge_index is really int32, reading it as int64 packs two indices into one
// word -> out-of-range with overwhelming probability over 1024 words.
__global__ void prep_kernel(const void* ei) {
    int i = blockIdx.x * blockDim.x + threadIdx.x;
    if (i < NN) g_cnt[i] = 0;
    if (i == 0) g_total = 0;
    if (blockIdx.x == 0 && threadIdx.x < 32) {
        int lane = threadIdx.x;
        const long long* e64 = (const long long*)ei;
        int ok = 1;
        for (int t = lane; t < 1024; t += 32) {
            long long v = e64[t];
            if (v < 0 || v >= NN) ok = 0;
        }
        unsigned b = __ballot_sync(0xffffffffu, ok);
        if (lane == 0) g_is64 = (b == 0xffffffffu) ? 1 : 0;
    }
}

// ---------------- fused QKV projection + Minkowski self-products ----------
// block = 192 threads (thread = one output column among q|k|v), tile = 8 rows.
// Inner product accumulated as packed f32x2 pairs along K (FFMA2, 2x rate).
__global__ __launch_bounds__(192) void qkv_kernel(
    const float* __restrict__ x,
    const float* __restrict__ Wq, const float* __restrict__ bq,
    const float* __restrict__ Wk, const float* __restrict__ bk,
    const float* __restrict__ Wv, const float* __restrict__ bv)
{
    __shared__ __align__(16) float xs[8 * 128];
    int tid = threadIdx.x;
    int sel = tid >> 6;   // 0 -> q, 1 -> k, 2 -> v
    int cc  = tid & 63;

    const float* W;
    const float* bias;
    float* out;
    if (sel == 0)      { W = Wq; bias = bq; out = g_q; }
    else if (sel == 1) { W = Wk; bias = bk; out = g_k; }
    else               { W = Wv; bias = bv; out = g_v; }

    int tile = blockIdx.x;                  // 6250 tiles * 8 rows = 50000 exactly
    const float4* xg4 = (const float4*)(x + (size_t)tile * 8 * 128);
    float4* xs4 = (float4*)xs;
    for (int i = tid; i < 256; i += 192) xs4[i] = xg4[i];
    __syncthreads();

    unsigned long long acc[8];
#pragma unroll
    for (int r = 0; r < 8; r++) acc[r] = 0ull;

    const ulonglong2* Wr = (const ulonglong2*)(W + cc * 128);
    const ulonglong2* xs2 = (const ulonglong2*)xs;
#pragma unroll 4
    for (int k4 = 0; k4 < 32; k4++) {
        ulonglong2 w = Wr[k4];
#pragma unroll
        for (int r = 0; r < 8; r++) {
            ulonglong2 xv = xs2[r * 32 + k4];
            acc[r] = ffma2(w.x, xv.x, acc[r]);
            acc[r] = ffma2(w.y, xv.y, acc[r]);
        }
    }

    float b = bias[cc];
    float res[8];
#pragma unroll
    for (int r = 0; r < 8; r++) res[r] = unpack_sum(acc[r]) + b;

    int row0 = tile * 8;
#pragma unroll
    for (int r = 0; r < 8; r++) out[(row0 + r) * 64 + cc] = res[r];

    // fused Minkowski self-products for q and k: reduce over the 16 lanes of
    // each head (warp lanes span 32 consecutive cc -> lane group == head chunk)
    if (sel < 2) {
        float sign = ((cc & 15) == 15) ? -1.f : 1.f;
        float* dst = (sel == 0) ? g_qq : g_kk;
        int h = cc >> 4;
#pragma unroll
        for (int r = 0; r < 8; r++) {
            float p = res[r] * res[r] * sign;
            p += __shfl_xor_sync(0xffffffffu, p, 1);
            p += __shfl_xor_sync(0xffffffffu, p, 2);
            p += __shfl_xor_sync(0xffffffffu, p, 4);
            p += __shfl_xor_sync(0xffffffffu, p, 8);
            if ((cc & 15) == 0) dst[(row0 + r) * 4 + h] = p;
        }
    }
}

// ---------------- CSR build ----------------
// histogram: 2 edges per thread, vectorized index loads
__global__ void hist_kernel(const void* ei) {
    int is64 = g_is64;
    int t = blockIdx.x * blockDim.x + threadIdx.x;
    if (t >= EE / 2) return;
    int d0, d1;
    if (is64) {
        longlong2 d = ((const longlong2*)((const long long*)ei + EE))[t];
        d0 = (int)d.x; d1 = (int)d.y;
    } else {
        int2 d = ((const int2*)((const int*)ei + EE))[t];
        d0 = d.x; d1 = d.y;
    }
    atomicAdd(&g_cnt[d0], 1);
    atomicAdd(&g_cnt[d1], 1);
}

// range allocation: order-free replacement for the prefix scan. Each node gets
// a contiguous chunk [off, off+cnt) via one aggregated atomic (REDUX.SUM).
__global__ void alloc_kernel() {
    int i = blockIdx.x * blockDim.x + threadIdx.x;
    if (i >= NN) return;
    int c = g_cnt[i];
    int off = atomicAdd(&g_total, c);
    g_rs[i] = off;
    g_cur[i] = off;
}

// scatter: 2 edges per thread, vectorized index loads
__global__ void scatter_kernel(const void* ei) {
    int is64 = g_is64;
    int t = blockIdx.x * blockDim.x + threadIdx.x;
    if (t >= EE / 2) return;
    int s0, s1, d0, d1;
    if (is64) {
        const long long* e = (const long long*)ei;
        longlong2 sv = ((const longlong2*)e)[t];
        longlong2 dv = ((const longlong2*)(e + EE))[t];
        s0 = (int)sv.x; s1 = (int)sv.y;
        d0 = (int)dv.x; d1 = (int)dv.y;
    } else {
        const int* e = (const int*)ei;
        int2 sv = ((const int2*)e)[t];
        int2 dv = ((const int2*)(e + EE))[t];
        s0 = sv.x; s1 = sv.y;
        d0 = dv.x; d1 = dv.y;
    }
    g_csr[atomicAdd(&g_cur[d0], 1)] = s0;
    g_csr[atomicAdd(&g_cur[d1], 1)] = s1;
}

// ---------------- gather attention: one warp per dst node --------------------
// lane l owns flat features {2l, 2l+1}; head h = l/8; 8-lane groups reduce dots.
// exp(-acosh(arg)) == 1/(arg + sqrt(arg^2-1))  -> no MUFU log/exp at all.
// Softmax denom cancels exactly into the L2 norm: att = S / (||S|| + EPS*s),
// and the max-shift cancels too (scale invariance), so no online max needed.
__global__ __launch_bounds__(256) void attn_kernel() {
    int gtid = blockIdx.x * blockDim.x + threadIdx.x;
    int i = gtid >> 5;
    if (i >= NN) return;
    int lane = threadIdx.x & 31;
    int h  = lane >> 3;
    int dp = lane & 7;

    float2 kv = *(const float2*)(g_k + i * 64 + 2 * lane);
    float sign = (dp == 7) ? -1.f : 1.f;   // flat dim 15 carries Minkowski minus
    float kkv = g_kk[i * 4 + h];

    int js = g_rs[i];
    int je = js + g_cnt[i];

    float s = 0.f, a0 = 0.f, a1 = 0.f;

    int j = js;
    for (; j + 3 < je; j += 4) {
        int s0 = g_csr[j];
        int s1 = g_csr[j + 1];
        int s2 = g_csr[j + 2];
        int s3 = g_csr[j + 3];
        float2 q0 = *(const float2*)(g_q + s0 * 64 + 2 * lane);
        float2 q1 = *(const float2*)(g_q + s1 * 64 + 2 * lane);
        float2 q2 = *(const float2*)(g_q + s2 * 64 + 2 * lane);
        float2 q3 = *(const float2*)(g_q + s3 * 64 + 2 * lane);
        float2 v0 = *(const float2*)(g_v + s0 * 64 + 2 * lane);
        float2 v1 = *(const float2*)(g_v + s1 * 64 + 2 * lane);
        float2 v2 = *(const float2*)(g_v + s2 * 64 + 2 * lane);
        float2 v3 = *(const float2*)(g_v + s3 * 64 + 2 * lane);
        float qq0 = g_qq[s0 * 4 + h];
        float qq1 = g_qq[s1 * 4 + h];
        float qq2 = g_qq[s2 * 4 + h];
        float qq3 = g_qq[s3 * 4 + h];

        float d0 = fmaf(q0.x, kv.x, sign * q0.y * kv.y);
        float d1 = fmaf(q1.x, kv.x, sign * q1.y * kv.y);
        float d2 = fmaf(q2.x, kv.x, sign * q2.y * kv.y);
        float d3 = fmaf(q3.x, kv.x, sign * q3.y * kv.y);
        d0 += __shfl_xor_sync(0xffffffffu, d0, 1);
        d1 += __shfl_xor_sync(0xffffffffu, d1, 1);
        d2 += __shfl_xor_sync(0xffffffffu, d2, 1);
        d3 += __shfl_xor_sync(0xffffffffu, d3, 1);
        d0 += __shfl_xor_sync(0xffffffffu, d0, 2);
        d1 += __shfl_xor_sync(0xffffffffu, d1, 2);
        d2 += __shfl_xor_sync(0xffffffffu, d2, 2);
        d3 += __shfl_xor_sync(0xffffffffu, d3, 2);
        d0 += __shfl_xor_sync(0xffffffffu, d0, 4);
        d1 += __shfl_xor_sync(0xffffffffu, d1, 4);
        d2 += __shfl_xor_sync(0xffffffffu, d2, 4);
        d3 += __shfl_xor_sync(0xffffffffu, d3, 4);

        float r0 = __fdividef(d0 * d0, fmaxf(fabsf(qq0 * kkv), 1e-9f));
        float r1 = __fdividef(d1 * d1, fmaxf(fabsf(qq1 * kkv), 1e-9f));
        float r2 = __fdividef(d2 * d2, fmaxf(fabsf(qq2 * kkv), 1e-9f));
        float r3 = __fdividef(d3 * d3, fmaxf(fabsf(qq3 * kkv), 1e-9f));
        float g0 = fmaxf(sqrtf(r0 + 1e-9f), 1.0f + 1e-6f);
        float g1 = fmaxf(sqrtf(r1 + 1e-9f), 1.0f + 1e-6f);
        float g2 = fmaxf(sqrtf(r2 + 1e-9f), 1.0f + 1e-6f);
        float g3 = fmaxf(sqrtf(r3 + 1e-9f), 1.0f + 1e-6f);
        float p0 = __frcp_rn(g0 + sqrtf(fmaf(g0, g0, -1.0f)));
        float p1 = __frcp_rn(g1 + sqrtf(fmaf(g1, g1, -1.0f)));
        float p2 = __frcp_rn(g2 + sqrtf(fmaf(g2, g2, -1.0f)));
        float p3 = __frcp_rn(g3 + sqrtf(fmaf(g3, g3, -1.0f)));

        s += (p0 + p1) + (p2 + p3);
        a0 = fmaf(p0, v0.x, fmaf(p1, v1.x, fmaf(p2, v2.x, fmaf(p3, v3.x, a0))));
        a1 = fmaf(p0, v0.y, fmaf(p1, v1.y, fmaf(p2, v2.y, fmaf(p3, v3.y, a1))));
    }
    for (; j < je; j++) {
        int s0 = g_csr[j];
        float2 q0 = *(const float2*)(g_q + s0 * 64 + 2 * lane);
        float d0 = fmaf(q0.x, kv.x, sign * q0.y * kv.y);
        d0 += __shfl_xor_sync(0xffffffffu, d0, 1);
        d0 += __shfl_xor_sync(0xffffffffu, d0, 2);
        d0 += __shfl_xor_sync(0xffffffffu, d0, 4);
        float qq0 = g_qq[s0 * 4 + h];
        float2 v0 = *(const float2*)(g_v + s0 * 64 + 2 * lane);
        float r0 = __fdividef(d0 * d0, fmaxf(fabsf(qq0 * kkv), 1e-9f));
        float g0 = fmaxf(sqrtf(r0 + 1e-9f), 1.0f + 1e-6f);
        float p0 = __frcp_rn(g0 + sqrtf(fmaf(g0, g0, -1.0f)));
        s += p0;
        a0 = fmaf(p0, v0.x, a0);
        a1 = fmaf(p0, v0.y, a1);
    }

    float nsq = fmaf(a0, a0, a1 * a1);
    nsq += __shfl_xor_sync(0xffffffffu, nsq, 1);
    nsq += __shfl_xor_sync(0xffffffffu, nsq, 2);
    nsq += __shfl_xor_sync(0xffffffffu, nsq, 4);
    float norm = sqrtf(nsq);
    // agg = S/s, attended = agg/(||agg||+EPS) = S/(||S|| + EPS*s); 0 if no mass
    float scale = (norm > 0.f) ? __frcp_rn(norm + 1e-9f * s) : 0.f;
    float2 o;
    o.x = a0 * scale;
    o.y = a1 * scale;
    *(float2*)(g_att + i * 64 + 2 * lane) = o;
}

// ---------------- output projection: [N,64] x [64,64]^T + bias --------------
// 256-thread blocks = 4 independent 16-row tiles (64 columns each), FFMA2.
__global__ __launch_bounds__(256) void out_kernel(
    const float* __restrict__ Wo, const float* __restrict__ bo,
    float* __restrict__ out)
{
    __shared__ __align__(16) float as[4][16 * 64];
    int grp = threadIdx.x >> 6;     // tile within block
    int tid = threadIdx.x & 63;     // column
    int tile = blockIdx.x * 4 + grp;
    if (tile >= 3125) return;       // 3125 tiles * 16 rows = 50000

    const float4* ag = (const float4*)(g_att + (size_t)tile * 16 * 64);
    float4* as4 = (float4*)as[grp];
    for (int i = tid; i < 256; i += 64) as4[i] = ag[i];
    __syncthreads();

    unsigned long long acc[16];
#pragma unroll
    for (int r = 0; r < 16; r++) acc[r] = 0ull;

    const ulonglong2* Wr = (const ulonglong2*)(Wo + tid * 64);
    const ulonglong2* as2 = (const ulonglong2*)as[grp];
#pragma unroll 4
    for (int k4 = 0; k4 < 16; k4++) {
        ulonglong2 w = Wr[k4];
#pragma unroll
        for (int r = 0; r < 16; r++) {
            ulonglong2 a = as2[r * 16 + k4];
            acc[r] = ffma2(w.x, a.x, acc[r]);
            acc[r] = ffma2(w.y, a.y, acc[r]);
        }
    }

    float b = bo[tid];
    int row0 = tile * 16;
#pragma unroll
    for (int r = 0; r < 16; r++) out[(row0 + r) * 64 + tid] = unpack_sum(acc[r]) + b;
}

// ---------------- launch ----------------
extern "C" void kernel_launch(void* const* d_in, const int* in_sizes, int n_in,
                              void* d_out, int out_size) {
    const float* x  = (const float*)d_in[0];
    const void*  ei = d_in[1];
    const float* Wq = (const float*)d_in[2];
    const float* bq = (const float*)d_in[3];
    const float* Wk = (const float*)d_in[4];
    const float* bk = (const float*)d_in[5];
    const float* Wv = (const float*)d_in[6];
    const float* bv = (const float*)d_in[7];
    const float* Wo = (const float*)d_in[8];
    const float* bo = (const float*)d_in[9];
    float* out = (float*)d_out;

    prep_kernel<<<(NN + 255) / 256, 256>>>(ei);
    qkv_kernel<<<NN / 8, 192>>>(x, Wq, bq, Wk, bk, Wv, bv);
    hist_kernel<<<(EE / 2 + 255) / 256, 256>>>(ei);
    alloc_kernel<<<(NN + 255) / 256, 256>>>();
    scatter_kernel<<<(EE / 2 + 255) / 256, 256>>>(ei);
    attn_kernel<<<(NN * 32) / 256, 256>>>();
    out_kernel<<<(3125 + 3) / 4, 256>>>(Wo, bo, out);
}